// round 11
// baseline (speedup 1.0000x reference)
#include <cuda_runtime.h>
#include <cuda_fp16.h>
#include <math.h>

#define NN 50000
#define NE 1600000
#define DD 128
#define HC 64    // H*C = 2*32
#define CAP 128  // max degree per bucket (mean 32, sigma ~5.7)

// ---------------- scratch (no allocation allowed) ----------------
__device__ __half  g_xs[2][NN * HC];    // fp16 message tables (6.4MB/side)
__device__ float2  g_als[2][NN];        // xs·att_src per head (fp32, pre-quantization)
__device__ float2  g_ald[2][NN];        // indexed by DIRECTION
__device__ float4  g_wv[DD];            // {ws_h0, ws_h1, wd_h0, wd_h1}
__device__ int     g_cnt[2][NN];
__device__ int     g_bkt[2][NN * CAP];  // fixed-capacity adjacency buckets
__device__ int     g_is64;

__device__ __forceinline__ float eluf(float x) {
    return x > 0.f ? x : (__expf(x) - 1.f);
}
__device__ __forceinline__ float lrelu(float a) {
    return a > 0.f ? a : 0.2f * a;
}

__global__ void k_warm() {}

// ---------------- 1. zero counters + dtype detect ----------------
__global__ void k_init(const void* ei) {
    int i = blockIdx.x * blockDim.x + threadIdx.x;
    if (i < 2 * NN) ((int*)g_cnt)[i] = 0;
    if (blockIdx.x == 0 && threadIdx.x == 0) {
        const int4* p = (const int4*)ei;
        int nz = 0;
        #pragma unroll
        for (int k = 0; k < 32; k++) { int4 v = p[k]; nz |= v.y | v.w; }
        g_is64 = (nz == 0) ? 1 : 0;
    }
}

// ---------------- 2. single-pass bucket scatter (4 edges/thread) ----------------
__global__ void k_scatter(const void* __restrict__ ei) {
    int base = (blockIdx.x * blockDim.x + threadIdx.x) * 4;
    if (base >= NE) return;
    int s[4], d[4];
    if (g_is64) {
        const long long* p = (const long long*)ei;
        #pragma unroll
        for (int k = 0; k < 4; k++) { s[k] = (int)p[base + k]; d[k] = (int)p[NE + base + k]; }
    } else {
        const int* p = (const int*)ei;
        int4 sv = *(const int4*)(p + base);
        int4 dv = *(const int4*)(p + NE + base);
        s[0] = sv.x; s[1] = sv.y; s[2] = sv.z; s[3] = sv.w;
        d[0] = dv.x; d[1] = dv.y; d[2] = dv.z; d[3] = dv.w;
    }
    #pragma unroll
    for (int k = 0; k < 4; k++) {
        if ((unsigned)s[k] < NN && (unsigned)d[k] < NN) {
            int p0 = atomicAdd(&g_cnt[0][d[k]], 1);
            if (p0 < CAP) g_bkt[0][d[k] * CAP + p0] = s[k];
            int p1 = atomicAdd(&g_cnt[1][s[k]], 1);
            if (p1 < CAP) g_bkt[1][s[k] * CAP + p1] = d[k];
        }
    }
}

// ---------------- 3. fused attention-vector precompute ----------------
__global__ void k_prep(const float* __restrict__ Wsrc, const float* __restrict__ Wdst,
                       const float* __restrict__ attS, const float* __restrict__ attD) {
    int k = threadIdx.x;
    float a0 = 0.f, a1 = 0.f, a2 = 0.f, a3 = 0.f;
    #pragma unroll 8
    for (int c = 0; c < 32; c++) {
        a0 = fmaf(Wsrc[k * 64 + c],      attS[c],      a0);
        a1 = fmaf(Wsrc[k * 64 + 32 + c], attS[32 + c], a1);
        a2 = fmaf(Wdst[k * 64 + c],      attD[c],      a2);
        a3 = fmaf(Wdst[k * 64 + 32 + c], attD[32 + c], a3);
    }
    g_wv[k] = make_float4(a0, a1, a2, a3);
}

// ---------------- 4. elu + x @ W_src + attention coefficients ----------------
__global__ void k_gemm(const float* __restrict__ hx, const float* __restrict__ tx,
                       const float* __restrict__ Wsrc, const float* __restrict__ attS) {
    __shared__ float Wc[128 * 64];   // [k][c]   32KB
    __shared__ float xt[32 * 128];   // [row][k] 16KB
    __shared__ float Av[64];
    int side = blockIdx.y;
    const float* X = side ? tx : hx;
    __half* XS = g_xs[side];
    float2* ALS = g_als[side];
    float2* ALD = g_ald[side ^ 1];

    int tid = threadIdx.x;
    for (int i = tid; i < 128 * 64; i += 256) Wc[i] = Wsrc[i];
    if (tid < 64) Av[tid] = attS[tid];

    int warp = tid >> 5, lane = tid & 31;
    float4 wz, ww;
    {
        float4 w0 = g_wv[lane * 4 + 0];
        float4 w1 = g_wv[lane * 4 + 1];
        float4 w2 = g_wv[lane * 4 + 2];
        float4 w3 = g_wv[lane * 4 + 3];
        wz = make_float4(w0.z, w1.z, w2.z, w3.z);
        ww = make_float4(w0.w, w1.w, w2.w, w3.w);
    }

    int ntiles = (NN + 31) / 32;
    for (int tile = blockIdx.x; tile < ntiles; tile += gridDim.x) {
        __syncthreads();
        int r0 = tile * 32;
        for (int i = tid; i < 32 * 32; i += 256) {
            int row = i >> 5, q = i & 31;
            float4 v = make_float4(0.f, 0.f, 0.f, 0.f);
            int gr = r0 + row;
            if (gr < NN) v = ((const float4*)X)[gr * 32 + q];
            v.x = eluf(v.x); v.y = eluf(v.y); v.z = eluf(v.z); v.w = eluf(v.w);
            ((float4*)xt)[i] = v;
        }
        __syncthreads();

        int rb = warp * 4;
        const float* xr = xt + rb * 128;
        float2 a0 = {0.f,0.f}, a1 = {0.f,0.f}, a2 = {0.f,0.f}, a3 = {0.f,0.f};
        #pragma unroll 8
        for (int k = 0; k < 128; k += 4) {
            float4 x0 = *(const float4*)&xr[k];
            float4 x1 = *(const float4*)&xr[128 + k];
            float4 x2 = *(const float4*)&xr[256 + k];
            float4 x3 = *(const float4*)&xr[384 + k];
            #pragma unroll
            for (int j = 0; j < 4; j++) {
                float2 w = *(const float2*)&Wc[(k + j) * 64 + lane * 2];
                float v0 = j == 0 ? x0.x : j == 1 ? x0.y : j == 2 ? x0.z : x0.w;
                float v1 = j == 0 ? x1.x : j == 1 ? x1.y : j == 2 ? x1.z : x1.w;
                float v2 = j == 0 ? x2.x : j == 1 ? x2.y : j == 2 ? x2.z : x2.w;
                float v3 = j == 0 ? x3.x : j == 1 ? x3.y : j == 2 ? x3.z : x3.w;
                a0.x = fmaf(v0, w.x, a0.x); a0.y = fmaf(v0, w.y, a0.y);
                a1.x = fmaf(v1, w.x, a1.x); a1.y = fmaf(v1, w.y, a1.y);
                a2.x = fmaf(v2, w.x, a2.x); a2.y = fmaf(v2, w.y, a2.y);
                a3.x = fmaf(v3, w.x, a3.x); a3.y = fmaf(v3, w.y, a3.y);
            }
        }
        int g = r0 + rb;
        if (g + 0 < NN) ((half2*)XS)[(g + 0) * 32 + lane] = __floats2half2_rn(a0.x, a0.y);
        if (g + 1 < NN) ((half2*)XS)[(g + 1) * 32 + lane] = __floats2half2_rn(a1.x, a1.y);
        if (g + 2 < NN) ((half2*)XS)[(g + 2) * 32 + lane] = __floats2half2_rn(a2.x, a2.y);
        if (g + 3 < NN) ((half2*)XS)[(g + 3) * 32 + lane] = __floats2half2_rn(a3.x, a3.y);

        float avx = Av[lane * 2], avy = Av[lane * 2 + 1];
        #pragma unroll
        for (int r = 0; r < 4; r++) {
            float2 a = r == 0 ? a0 : r == 1 ? a1 : r == 2 ? a2 : a3;
            float v = a.x * avx + a.y * avy;
            #pragma unroll
            for (int off = 8; off; off >>= 1)
                v += __shfl_xor_sync(0xffffffffu, v, off);
            float v16 = __shfl_sync(0xffffffffu, v, 16);

            float4 xv = *(const float4*)&xr[r * 128 + lane * 4];
            float d0 = xv.x * wz.x + xv.y * wz.y + xv.z * wz.z + xv.w * wz.w;
            float d1 = xv.x * ww.x + xv.y * ww.y + xv.z * ww.z + xv.w * ww.w;
            #pragma unroll
            for (int off = 16; off; off >>= 1) {
                d0 += __shfl_xor_sync(0xffffffffu, d0, off);
                d1 += __shfl_xor_sync(0xffffffffu, d1, off);
            }
            if (lane == 0 && g + r < NN) {
                ALS[g + r] = make_float2(v, v16);
                ALD[g + r] = make_float2(d0, d1);
            }
        }
    }
}

// ---------------- 5. aggregation: 8 lanes/edge, 4 edges in parallel ----------------
// lane&7 = 8-channel group (16B of fp16), lane>>3 = edge-within-quad
__device__ __forceinline__ void fma8(float* a, float w, uint4 r) {
    float2 f0 = __half22float2(*(__half2*)&r.x);
    float2 f1 = __half22float2(*(__half2*)&r.y);
    float2 f2 = __half22float2(*(__half2*)&r.z);
    float2 f3 = __half22float2(*(__half2*)&r.w);
    a[0] = fmaf(w, f0.x, a[0]); a[1] = fmaf(w, f0.y, a[1]);
    a[2] = fmaf(w, f1.x, a[2]); a[3] = fmaf(w, f1.y, a[3]);
    a[4] = fmaf(w, f2.x, a[4]); a[5] = fmaf(w, f2.y, a[5]);
    a[6] = fmaf(w, f3.x, a[6]); a[7] = fmaf(w, f3.y, a[7]);
}

__global__ void k_agg(const float* __restrict__ bias, float* __restrict__ out) {
    int dir = blockIdx.y;
    int n = blockIdx.x * (blockDim.x >> 5) + (threadIdx.x >> 5);
    if (n >= NN) return;
    int lane = threadIdx.x & 31;
    int ch8 = lane & 7;              // uint4 index within the 64-half row
    int q   = lane >> 3;             // edge slot 0-3
    bool head1 = ch8 >= 4;           // channels 32..63 -> head 1

    const __half*  xs  = g_xs[dir];
    const float2* als = g_als[dir];
    float2 aldn = g_ald[dir][n];
    float2 alsn = als[n];

    // self loop (no max shift; |alpha| is O(10))
    float ps0 = __expf(lrelu(alsn.x + aldn.x));
    float ps1 = __expf(lrelu(alsn.y + aldn.y));
    float s0 = ps0, s1 = ps1;
    float a[8] = {0.f,0.f,0.f,0.f,0.f,0.f,0.f,0.f};
    if (q == 0) {
        uint4 xn = ((const uint4*)xs)[n * 8 + ch8];
        fma8(a, head1 ? ps1 : ps0, xn);
    }

    int deg = min(g_cnt[dir][n], CAP);
    const int* adj = g_bkt[dir] + n * CAP;

    for (int base = 0; base < deg; base += 32) {
        int j = base + lane;
        int sv = 0;
        float p0 = 0.f, p1 = 0.f;
        if (j < deg) {
            sv = adj[j];
            float2 av = als[sv];
            p0 = __expf(lrelu(av.x + aldn.x));
            p1 = __expf(lrelu(av.y + aldn.y));
        }
        float t0 = p0, t1 = p1;
        #pragma unroll
        for (int off = 16; off; off >>= 1) {
            t0 += __shfl_xor_sync(0xffffffffu, t0, off);
            t1 += __shfl_xor_sync(0xffffffffu, t1, off);
        }
        s0 += t0;
        s1 += t1;

        int cnt = min(32, deg - base);
        int i = 0;
        // 8 edges / iteration: 2 independent row loads per lane
        for (; i + 8 <= cnt; i += 8) {
            int eA = i + q, eB = i + 4 + q;
            int   sA  = __shfl_sync(0xffffffffu, sv, eA);
            float a0v = __shfl_sync(0xffffffffu, p0, eA);
            float a1v = __shfl_sync(0xffffffffu, p1, eA);
            int   sB  = __shfl_sync(0xffffffffu, sv, eB);
            float b0v = __shfl_sync(0xffffffffu, p0, eB);
            float b1v = __shfl_sync(0xffffffffu, p1, eB);
            uint4 rA = ((const uint4*)xs)[sA * 8 + ch8];
            uint4 rB = ((const uint4*)xs)[sB * 8 + ch8];
            fma8(a, head1 ? a1v : a0v, rA);
            fma8(a, head1 ? b1v : b0v, rB);
        }
        for (; i < cnt; i += 4) {
            int e = i + q;
            int ee = e & 31;
            int   sA  = __shfl_sync(0xffffffffu, sv, ee);
            float w0  = __shfl_sync(0xffffffffu, p0, ee);
            float w1  = __shfl_sync(0xffffffffu, p1, ee);
            float w = head1 ? w1 : w0;
            if (e >= cnt) w = 0.f;
            uint4 rA = ((const uint4*)xs)[sA * 8 + ch8];
            fma8(a, w, rA);
        }
    }

    // combine the 4 edge-slot accumulators (reduce over lane bits 3,4)
    #pragma unroll
    for (int k = 0; k < 8; k++) {
        a[k] += __shfl_xor_sync(0xffffffffu, a[k], 8);
        a[k] += __shfl_xor_sync(0xffffffffu, a[k], 16);
    }

    if (lane < 8) {
        float inv = 1.f / ((head1 ? s1 : s0) + 1e-16f);
        float4 b0 = ((const float4*)bias)[ch8 * 2];
        float4 b1 = ((const float4*)bias)[ch8 * 2 + 1];
        float* op = out + (dir == 0 ? (size_t)NN * 64 : 0) + (size_t)n * 64;
        float4 o0, o1;
        o0.x = a[0] * inv + b0.x; o0.y = a[1] * inv + b0.y;
        o0.z = a[2] * inv + b0.z; o0.w = a[3] * inv + b0.w;
        o1.x = a[4] * inv + b1.x; o1.y = a[5] * inv + b1.y;
        o1.z = a[6] * inv + b1.z; o1.w = a[7] * inv + b1.w;
        ((float4*)op)[ch8 * 2]     = o0;
        ((float4*)op)[ch8 * 2 + 1] = o1;
    }
}

// ---------------- stream/event setup at static init (outside capture) ----------------
static cudaStream_t g_s2;
static cudaEvent_t  g_evF, g_evJ;
namespace {
struct _StreamInit {
    _StreamInit() {
        cudaStreamCreateWithFlags(&g_s2, cudaStreamNonBlocking);
        cudaEventCreateWithFlags(&g_evF, cudaEventDisableTiming);
        cudaEventCreateWithFlags(&g_evJ, cudaEventDisableTiming);
        k_warm<<<1, 1, 0, g_s2>>>();
        cudaStreamSynchronize(g_s2);
    }
} _streamInit;
}

// ---------------- launch ----------------
extern "C" void kernel_launch(void* const* d_in, const int* in_sizes, int n_in,
                              void* d_out, int out_size) {
    const float* hx   = (const float*)d_in[0];
    const float* tx   = (const float*)d_in[1];
    const void*  ei   = d_in[2];
    const float* Wsrc = (const float*)d_in[3];
    const float* Wdst = (const float*)d_in[4];
    const float* attS = (const float*)d_in[5];
    const float* attD = (const float*)d_in[6];
    const float* bias = (const float*)d_in[7];
    float* out = (float*)d_out;

    // fork: dense chain on g_s2, bucket-scatter chain on the main stream
    cudaEventRecord(g_evF, 0);
    cudaStreamWaitEvent(g_s2, g_evF, 0);
    k_prep<<<1, 128, 0, g_s2>>>(Wsrc, Wdst, attS, attD);
    k_gemm<<<dim3(296, 2), 256, 0, g_s2>>>(hx, tx, Wsrc, attS);
    cudaEventRecord(g_evJ, g_s2);

    k_init<<<(2 * NN + 255) / 256, 256>>>(ei);
    k_scatter<<<(NE / 4 + 255) / 256, 256>>>(ei);

    cudaStreamWaitEvent(0, g_evJ, 0);   // join
    k_agg<<<dim3((NN + 7) / 8, 2), 256>>>(bias, out);
}

// round 12
// speedup vs baseline: 1.0097x; 1.0097x over previous
#include <cuda_runtime.h>
#include <cuda_fp16.h>
#include <math.h>

#define NN 50000
#define NE 1600000
#define DD 128
#define HC 64    // H*C = 2*32
#define CAP 128  // max degree per bucket (mean 32, sigma ~5.7)

// ---------------- scratch (no allocation allowed) ----------------
__device__ __half  g_xs[2][NN * HC];    // fp16 message tables (6.4MB/side)
__device__ float2  g_als[2][NN];        // xs·att_src per head (fp32, pre-quantization)
__device__ float2  g_ald[2][NN];        // indexed by DIRECTION
__device__ float4  g_wv[DD];            // {ws_h0, ws_h1, wd_h0, wd_h1}
__device__ int     g_cnt[2][NN];
__device__ int     g_bkt[2][NN * CAP];  // fixed-capacity adjacency buckets
__device__ int     g_is64;

__device__ __forceinline__ float eluf(float x) {
    return x > 0.f ? x : (__expf(x) - 1.f);
}
__device__ __forceinline__ float lrelu(float a) {
    return a > 0.f ? a : 0.2f * a;
}

__global__ void k_warm() {}

// ---------------- 1. zero counters + dtype detect ----------------
__global__ void k_init(const void* ei) {
    int i = blockIdx.x * blockDim.x + threadIdx.x;
    if (i < 2 * NN) ((int*)g_cnt)[i] = 0;
    if (blockIdx.x == 0 && threadIdx.x == 0) {
        const int4* p = (const int4*)ei;
        int nz = 0;
        #pragma unroll
        for (int k = 0; k < 32; k++) { int4 v = p[k]; nz |= v.y | v.w; }
        g_is64 = (nz == 0) ? 1 : 0;
    }
}

// ---------------- 2. single-pass bucket scatter (4 edges/thread) ----------------
__global__ void k_scatter(const void* __restrict__ ei) {
    int base = (blockIdx.x * blockDim.x + threadIdx.x) * 4;
    if (base >= NE) return;
    int s[4], d[4];
    if (g_is64) {
        const long long* p = (const long long*)ei;
        #pragma unroll
        for (int k = 0; k < 4; k++) { s[k] = (int)p[base + k]; d[k] = (int)p[NE + base + k]; }
    } else {
        const int* p = (const int*)ei;
        int4 sv = *(const int4*)(p + base);
        int4 dv = *(const int4*)(p + NE + base);
        s[0] = sv.x; s[1] = sv.y; s[2] = sv.z; s[3] = sv.w;
        d[0] = dv.x; d[1] = dv.y; d[2] = dv.z; d[3] = dv.w;
    }
    #pragma unroll
    for (int k = 0; k < 4; k++) {
        if ((unsigned)s[k] < NN && (unsigned)d[k] < NN) {
            int p0 = atomicAdd(&g_cnt[0][d[k]], 1);
            if (p0 < CAP) g_bkt[0][d[k] * CAP + p0] = s[k];
            int p1 = atomicAdd(&g_cnt[1][s[k]], 1);
            if (p1 < CAP) g_bkt[1][s[k] * CAP + p1] = d[k];
        }
    }
}

// ---------------- 3. fused attention-vector precompute ----------------
__global__ void k_prep(const float* __restrict__ Wsrc, const float* __restrict__ Wdst,
                       const float* __restrict__ attS, const float* __restrict__ attD) {
    int k = threadIdx.x;
    float a0 = 0.f, a1 = 0.f, a2 = 0.f, a3 = 0.f;
    #pragma unroll 8
    for (int c = 0; c < 32; c++) {
        a0 = fmaf(Wsrc[k * 64 + c],      attS[c],      a0);
        a1 = fmaf(Wsrc[k * 64 + 32 + c], attS[32 + c], a1);
        a2 = fmaf(Wdst[k * 64 + c],      attD[c],      a2);
        a3 = fmaf(Wdst[k * 64 + 32 + c], attD[32 + c], a3);
    }
    g_wv[k] = make_float4(a0, a1, a2, a3);
}

// ---------------- 4. elu + x @ W_src + attention coefficients ----------------
__global__ void k_gemm(const float* __restrict__ hx, const float* __restrict__ tx,
                       const float* __restrict__ Wsrc, const float* __restrict__ attS) {
    __shared__ float Wc[128 * 64];   // [k][c]   32KB
    __shared__ float xt[32 * 128];   // [row][k] 16KB
    __shared__ float Av[64];
    int side = blockIdx.y;
    const float* X = side ? tx : hx;
    __half* XS = g_xs[side];
    float2* ALS = g_als[side];
    float2* ALD = g_ald[side ^ 1];

    int tid = threadIdx.x;
    for (int i = tid; i < 128 * 64; i += 256) Wc[i] = Wsrc[i];
    if (tid < 64) Av[tid] = attS[tid];

    int warp = tid >> 5, lane = tid & 31;
    float4 wz, ww;
    {
        float4 w0 = g_wv[lane * 4 + 0];
        float4 w1 = g_wv[lane * 4 + 1];
        float4 w2 = g_wv[lane * 4 + 2];
        float4 w3 = g_wv[lane * 4 + 3];
        wz = make_float4(w0.z, w1.z, w2.z, w3.z);
        ww = make_float4(w0.w, w1.w, w2.w, w3.w);
    }

    int ntiles = (NN + 31) / 32;
    for (int tile = blockIdx.x; tile < ntiles; tile += gridDim.x) {
        __syncthreads();
        int r0 = tile * 32;
        for (int i = tid; i < 32 * 32; i += 256) {
            int row = i >> 5, q = i & 31;
            float4 v = make_float4(0.f, 0.f, 0.f, 0.f);
            int gr = r0 + row;
            if (gr < NN) v = ((const float4*)X)[gr * 32 + q];
            v.x = eluf(v.x); v.y = eluf(v.y); v.z = eluf(v.z); v.w = eluf(v.w);
            ((float4*)xt)[i] = v;
        }
        __syncthreads();

        int rb = warp * 4;
        const float* xr = xt + rb * 128;
        float2 a0 = {0.f,0.f}, a1 = {0.f,0.f}, a2 = {0.f,0.f}, a3 = {0.f,0.f};
        #pragma unroll 8
        for (int k = 0; k < 128; k += 4) {
            float4 x0 = *(const float4*)&xr[k];
            float4 x1 = *(const float4*)&xr[128 + k];
            float4 x2 = *(const float4*)&xr[256 + k];
            float4 x3 = *(const float4*)&xr[384 + k];
            #pragma unroll
            for (int j = 0; j < 4; j++) {
                float2 w = *(const float2*)&Wc[(k + j) * 64 + lane * 2];
                float v0 = j == 0 ? x0.x : j == 1 ? x0.y : j == 2 ? x0.z : x0.w;
                float v1 = j == 0 ? x1.x : j == 1 ? x1.y : j == 2 ? x1.z : x1.w;
                float v2 = j == 0 ? x2.x : j == 1 ? x2.y : j == 2 ? x2.z : x2.w;
                float v3 = j == 0 ? x3.x : j == 1 ? x3.y : j == 2 ? x3.z : x3.w;
                a0.x = fmaf(v0, w.x, a0.x); a0.y = fmaf(v0, w.y, a0.y);
                a1.x = fmaf(v1, w.x, a1.x); a1.y = fmaf(v1, w.y, a1.y);
                a2.x = fmaf(v2, w.x, a2.x); a2.y = fmaf(v2, w.y, a2.y);
                a3.x = fmaf(v3, w.x, a3.x); a3.y = fmaf(v3, w.y, a3.y);
            }
        }
        int g = r0 + rb;
        if (g + 0 < NN) ((half2*)XS)[(g + 0) * 32 + lane] = __floats2half2_rn(a0.x, a0.y);
        if (g + 1 < NN) ((half2*)XS)[(g + 1) * 32 + lane] = __floats2half2_rn(a1.x, a1.y);
        if (g + 2 < NN) ((half2*)XS)[(g + 2) * 32 + lane] = __floats2half2_rn(a2.x, a2.y);
        if (g + 3 < NN) ((half2*)XS)[(g + 3) * 32 + lane] = __floats2half2_rn(a3.x, a3.y);

        float avx = Av[lane * 2], avy = Av[lane * 2 + 1];
        #pragma unroll
        for (int r = 0; r < 4; r++) {
            float2 a = r == 0 ? a0 : r == 1 ? a1 : r == 2 ? a2 : a3;
            float v = a.x * avx + a.y * avy;
            #pragma unroll
            for (int off = 8; off; off >>= 1)
                v += __shfl_xor_sync(0xffffffffu, v, off);
            float v16 = __shfl_sync(0xffffffffu, v, 16);

            float4 xv = *(const float4*)&xr[r * 128 + lane * 4];
            float d0 = xv.x * wz.x + xv.y * wz.y + xv.z * wz.z + xv.w * wz.w;
            float d1 = xv.x * ww.x + xv.y * ww.y + xv.z * ww.z + xv.w * ww.w;
            #pragma unroll
            for (int off = 16; off; off >>= 1) {
                d0 += __shfl_xor_sync(0xffffffffu, d0, off);
                d1 += __shfl_xor_sync(0xffffffffu, d1, off);
            }
            if (lane == 0 && g + r < NN) {
                ALS[g + r] = make_float2(v, v16);
                ALD[g + r] = make_float2(d0, d1);
            }
        }
    }
}

// ---------------- 5. aggregation: 8 lanes/edge, 4 edges in parallel ----------------
// lane&7 = 8-channel group (16B of fp16), lane>>3 = edge-within-quad
__device__ __forceinline__ void fma8(float* a, float w, uint4 r) {
    float2 f0 = __half22float2(*(__half2*)&r.x);
    float2 f1 = __half22float2(*(__half2*)&r.y);
    float2 f2 = __half22float2(*(__half2*)&r.z);
    float2 f3 = __half22float2(*(__half2*)&r.w);
    a[0] = fmaf(w, f0.x, a[0]); a[1] = fmaf(w, f0.y, a[1]);
    a[2] = fmaf(w, f1.x, a[2]); a[3] = fmaf(w, f1.y, a[3]);
    a[4] = fmaf(w, f2.x, a[4]); a[5] = fmaf(w, f2.y, a[5]);
    a[6] = fmaf(w, f3.x, a[6]); a[7] = fmaf(w, f3.y, a[7]);
}

__global__ void k_agg(const float* __restrict__ bias, float* __restrict__ out) {
    int dir = blockIdx.y;
    int n = blockIdx.x * (blockDim.x >> 5) + (threadIdx.x >> 5);
    if (n >= NN) return;
    int lane = threadIdx.x & 31;
    int ch8 = lane & 7;              // uint4 index within the 64-half row
    int q   = lane >> 3;             // edge slot 0-3
    bool head1 = ch8 >= 4;           // channels 32..63 -> head 1

    const __half*  xs  = g_xs[dir];
    const float2* als = g_als[dir];
    float2 aldn = g_ald[dir][n];
    float2 alsn = als[n];

    // self loop (no max shift; |alpha| is O(10))
    float ps0 = __expf(lrelu(alsn.x + aldn.x));
    float ps1 = __expf(lrelu(alsn.y + aldn.y));
    float s0 = ps0, s1 = ps1;
    float a[8] = {0.f,0.f,0.f,0.f,0.f,0.f,0.f,0.f};
    if (q == 0) {
        uint4 xn = ((const uint4*)xs)[n * 8 + ch8];
        fma8(a, head1 ? ps1 : ps0, xn);
    }

    int deg = min(g_cnt[dir][n], CAP);
    const int* adj = g_bkt[dir] + n * CAP;

    for (int base = 0; base < deg; base += 32) {
        int j = base + lane;
        int sv = 0;
        float p0 = 0.f, p1 = 0.f;
        if (j < deg) {
            sv = adj[j];
            float2 av = als[sv];
            p0 = __expf(lrelu(av.x + aldn.x));
            p1 = __expf(lrelu(av.y + aldn.y));
        }
        float t0 = p0, t1 = p1;
        #pragma unroll
        for (int off = 16; off; off >>= 1) {
            t0 += __shfl_xor_sync(0xffffffffu, t0, off);
            t1 += __shfl_xor_sync(0xffffffffu, t1, off);
        }
        s0 += t0;
        s1 += t1;

        int cnt = min(32, deg - base);
        int i = 0;
        // 8 edges / iteration: 2 independent row loads per lane
        for (; i + 8 <= cnt; i += 8) {
            int eA = i + q, eB = i + 4 + q;
            int   sA  = __shfl_sync(0xffffffffu, sv, eA);
            float a0v = __shfl_sync(0xffffffffu, p0, eA);
            float a1v = __shfl_sync(0xffffffffu, p1, eA);
            int   sB  = __shfl_sync(0xffffffffu, sv, eB);
            float b0v = __shfl_sync(0xffffffffu, p0, eB);
            float b1v = __shfl_sync(0xffffffffu, p1, eB);
            uint4 rA = ((const uint4*)xs)[sA * 8 + ch8];
            uint4 rB = ((const uint4*)xs)[sB * 8 + ch8];
            fma8(a, head1 ? a1v : a0v, rA);
            fma8(a, head1 ? b1v : b0v, rB);
        }
        for (; i < cnt; i += 4) {
            int e = i + q;
            int ee = e & 31;
            int   sA  = __shfl_sync(0xffffffffu, sv, ee);
            float w0  = __shfl_sync(0xffffffffu, p0, ee);
            float w1  = __shfl_sync(0xffffffffu, p1, ee);
            float w = head1 ? w1 : w0;
            if (e >= cnt) w = 0.f;
            uint4 rA = ((const uint4*)xs)[sA * 8 + ch8];
            fma8(a, w, rA);
        }
    }

    // combine the 4 edge-slot accumulators (reduce over lane bits 3,4)
    #pragma unroll
    for (int k = 0; k < 8; k++) {
        a[k] += __shfl_xor_sync(0xffffffffu, a[k], 8);
        a[k] += __shfl_xor_sync(0xffffffffu, a[k], 16);
    }

    if (lane < 8) {
        float inv = 1.f / ((head1 ? s1 : s0) + 1e-16f);
        float4 b0 = ((const float4*)bias)[ch8 * 2];
        float4 b1 = ((const float4*)bias)[ch8 * 2 + 1];
        float* op = out + (dir == 0 ? (size_t)NN * 64 : 0) + (size_t)n * 64;
        float4 o0, o1;
        o0.x = a[0] * inv + b0.x; o0.y = a[1] * inv + b0.y;
        o0.z = a[2] * inv + b0.z; o0.w = a[3] * inv + b0.w;
        o1.x = a[4] * inv + b1.x; o1.y = a[5] * inv + b1.y;
        o1.z = a[6] * inv + b1.z; o1.w = a[7] * inv + b1.w;
        ((float4*)op)[ch8 * 2]     = o0;
        ((float4*)op)[ch8 * 2 + 1] = o1;
    }
}

// ---------------- stream/event setup at static init (outside capture) ----------------
static cudaStream_t g_s2;
static cudaEvent_t  g_evF, g_evJ;
namespace {
struct _StreamInit {
    _StreamInit() {
        cudaStreamCreateWithFlags(&g_s2, cudaStreamNonBlocking);
        cudaEventCreateWithFlags(&g_evF, cudaEventDisableTiming);
        cudaEventCreateWithFlags(&g_evJ, cudaEventDisableTiming);
        k_warm<<<1, 1, 0, g_s2>>>();
        cudaStreamSynchronize(g_s2);
    }
} _streamInit;
}

// ---------------- launch ----------------
extern "C" void kernel_launch(void* const* d_in, const int* in_sizes, int n_in,
                              void* d_out, int out_size) {
    const float* hx   = (const float*)d_in[0];
    const float* tx   = (const float*)d_in[1];
    const void*  ei   = d_in[2];
    const float* Wsrc = (const float*)d_in[3];
    const float* Wdst = (const float*)d_in[4];
    const float* attS = (const float*)d_in[5];
    const float* attD = (const float*)d_in[6];
    const float* bias = (const float*)d_in[7];
    float* out = (float*)d_out;

    // fork: dense chain on g_s2, bucket-scatter chain on the main stream
    cudaEventRecord(g_evF, 0);
    cudaStreamWaitEvent(g_s2, g_evF, 0);
    k_prep<<<1, 128, 0, g_s2>>>(Wsrc, Wdst, attS, attD);
    k_gemm<<<dim3(296, 2), 256, 0, g_s2>>>(hx, tx, Wsrc, attS);
    cudaEventRecord(g_evJ, g_s2);

    k_init<<<(2 * NN + 255) / 256, 256>>>(ei);
    k_scatter<<<(NE / 4 + 255) / 256, 256>>>(ei);

    cudaStreamWaitEvent(0, g_evJ, 0);   // join
    k_agg<<<dim3((NN + 7) / 8, 2), 256>>>(bias, out);
}